// round 14
// baseline (speedup 1.0000x reference)
#include <cuda_runtime.h>
#include <cstdint>

// Gated delta-rule recurrent attention, single step. B=128, H=16, Dk=Dv=128.
//
// Round-13: two pipelined 32-col slices per CTA. r7 pays one barrier-reduce
// epoch per 16KB slice (4 warps idle on the slowest warp's loads before any
// store issues). Here each CTA owns BOTH slices of a (bh, half) pair:
// 16 front-batched LDG.128 at t0, then slice A's reduce/store runs while
// slice B's loads are still landing; ONE barrier covers both slices'
// partials. 3 barriers amortized over 32KB instead of 16KB.
//
// Grid 4096 x 128 threads, sA[8]+sB[8] register-resident (~100 regs),
// 5 CTAs/SM. __ldcs/__stcs, warp-shuffle pre-reduction as in r7.

#define BH   2048
#define DK   128
#define DV   128

__global__ __launch_bounds__(128, 5)
void delta_cell_kernel(const float* __restrict__ q,
                       const float* __restrict__ k,
                       const float* __restrict__ v,
                       const float* __restrict__ g,
                       const float* __restrict__ beta,
                       const float* __restrict__ state_in,
                       float* __restrict__ out,
                       float* __restrict__ state_out)
{
    const int bid  = blockIdx.x;         // 0..4095
    const int bh   = bid >> 1;           // (b*H + h)
    const int cb0  = (bid & 1) * 2;      // this CTA: column blocks cb0, cb0+1
    const int tid  = threadIdx.x;
    const int c4   = tid & 7;            // float4 col within a slice (0..7)
    const int rg   = tid >> 3;           // row group (0..15), rows 8rg..8rg+7
    const int warp = tid >> 5;           // 0..3

    __shared__ float  ks[DK];
    __shared__ float  qs[DK];
    __shared__ float4 red_kv [2][4][8];  // [slice][warp][c4]
    __shared__ float4 red_out[2][4][8];

    const float4* __restrict__ st4 =
        (const float4*)(state_in  + (size_t)bh * DK * DV);
    float4* __restrict__ sto4 =
        (float4*)(state_out + (size_t)bh * DK * DV);
    const int colA = cb0 * 8 + c4;       // float4 column of slice A
    const int colB = colA + 8;           // float4 column of slice B

    // ---- Front-batch all 16 state loads (both slices) at t0 ----
    float4 sA[8], sB[8];
#pragma unroll
    for (int j = 0; j < 8; ++j)
        sA[j] = __ldcs(&st4[(rg * 8 + j) * 32 + colA]);
#pragma unroll
    for (int j = 0; j < 8; ++j)
        sB[j] = __ldcs(&st4[(rg * 8 + j) * 32 + colB]);

    // Small tensors + k/q staging ride under the state-load latency.
    const float4 vtA  = ((const float4*)(v + (size_t)bh * DV))[colA];
    const float4 vtB  = ((const float4*)(v + (size_t)bh * DV))[colB];
    const float decay = expf(g[bh]);
    const float bet   = beta[bh];
    ks[tid] = k[bh * DK + tid];
    qs[tid] = q[bh * DK + tid];
    __syncthreads();

    // ---- k-dot partials: slice A first (waits only A's loads), then B
    //      (B's loads landed while A computed) ----
    float4 kvA = make_float4(0.f, 0.f, 0.f, 0.f);
#pragma unroll
    for (int j = 0; j < 8; ++j) {
        const float kk = ks[rg * 8 + j];
        kvA.x = fmaf(sA[j].x, kk, kvA.x);
        kvA.y = fmaf(sA[j].y, kk, kvA.y);
        kvA.z = fmaf(sA[j].z, kk, kvA.z);
        kvA.w = fmaf(sA[j].w, kk, kvA.w);
    }
    float4 kvB = make_float4(0.f, 0.f, 0.f, 0.f);
#pragma unroll
    for (int j = 0; j < 8; ++j) {
        const float kk = ks[rg * 8 + j];
        kvB.x = fmaf(sB[j].x, kk, kvB.x);
        kvB.y = fmaf(sB[j].y, kk, kvB.y);
        kvB.z = fmaf(sB[j].z, kk, kvB.z);
        kvB.w = fmaf(sB[j].w, kk, kvB.w);
    }
    // Collapse the 4 row-groups inside the warp (lane xor 8/16 keeps c4)
#pragma unroll
    for (int m = 8; m <= 16; m <<= 1) {
        kvA.x += __shfl_xor_sync(0xffffffffu, kvA.x, m);
        kvA.y += __shfl_xor_sync(0xffffffffu, kvA.y, m);
        kvA.z += __shfl_xor_sync(0xffffffffu, kvA.z, m);
        kvA.w += __shfl_xor_sync(0xffffffffu, kvA.w, m);
        kvB.x += __shfl_xor_sync(0xffffffffu, kvB.x, m);
        kvB.y += __shfl_xor_sync(0xffffffffu, kvB.y, m);
        kvB.z += __shfl_xor_sync(0xffffffffu, kvB.z, m);
        kvB.w += __shfl_xor_sync(0xffffffffu, kvB.w, m);
    }
    if ((tid & 31) < 8) {
        red_kv[0][warp][c4] = kvA;
        red_kv[1][warp][c4] = kvB;
    }
    __syncthreads();   // ONE barrier for both slices' partials

    // ---- Slice A: delta, update+store, q-dot ----
    float4 kvt = make_float4(0.f, 0.f, 0.f, 0.f);
#pragma unroll
    for (int w = 0; w < 4; ++w) {
        const float4 p = red_kv[0][w][c4];
        kvt.x += p.x; kvt.y += p.y; kvt.z += p.z; kvt.w += p.w;
    }
    float4 dA;
    dA.x = (vtA.x - decay * kvt.x) * bet;
    dA.y = (vtA.y - decay * kvt.y) * bet;
    dA.z = (vtA.z - decay * kvt.z) * bet;
    dA.w = (vtA.w - decay * kvt.w) * bet;

    float4 accA = make_float4(0.f, 0.f, 0.f, 0.f);
#pragma unroll
    for (int j = 0; j < 8; ++j) {
        const int row = rg * 8 + j;
        const float kk = ks[row];
        float4 sn;
        sn.x = fmaf(decay, sA[j].x, kk * dA.x);
        sn.y = fmaf(decay, sA[j].y, kk * dA.y);
        sn.z = fmaf(decay, sA[j].z, kk * dA.z);
        sn.w = fmaf(decay, sA[j].w, kk * dA.w);
        __stcs(&sto4[row * 32 + colA], sn);
        const float qq = qs[row];
        accA.x = fmaf(sn.x, qq, accA.x);
        accA.y = fmaf(sn.y, qq, accA.y);
        accA.z = fmaf(sn.z, qq, accA.z);
        accA.w = fmaf(sn.w, qq, accA.w);
    }

    // ---- Slice B: delta, update+store, q-dot ----
    kvt = make_float4(0.f, 0.f, 0.f, 0.f);
#pragma unroll
    for (int w = 0; w < 4; ++w) {
        const float4 p = red_kv[1][w][c4];
        kvt.x += p.x; kvt.y += p.y; kvt.z += p.z; kvt.w += p.w;
    }
    float4 dB;
    dB.x = (vtB.x - decay * kvt.x) * bet;
    dB.y = (vtB.y - decay * kvt.y) * bet;
    dB.z = (vtB.z - decay * kvt.z) * bet;
    dB.w = (vtB.w - decay * kvt.w) * bet;

    float4 accB = make_float4(0.f, 0.f, 0.f, 0.f);
#pragma unroll
    for (int j = 0; j < 8; ++j) {
        const int row = rg * 8 + j;
        const float kk = ks[row];
        float4 sn;
        sn.x = fmaf(decay, sB[j].x, kk * dB.x);
        sn.y = fmaf(decay, sB[j].y, kk * dB.y);
        sn.z = fmaf(decay, sB[j].z, kk * dB.z);
        sn.w = fmaf(decay, sB[j].w, kk * dB.w);
        __stcs(&sto4[row * 32 + colB], sn);
        const float qq = qs[row];
        accB.x = fmaf(sn.x, qq, accB.x);
        accB.y = fmaf(sn.y, qq, accB.y);
        accB.z = fmaf(sn.z, qq, accB.z);
        accB.w = fmaf(sn.w, qq, accB.w);
    }

    // ---- Output reductions, one barrier for both slices ----
#pragma unroll
    for (int m = 8; m <= 16; m <<= 1) {
        accA.x += __shfl_xor_sync(0xffffffffu, accA.x, m);
        accA.y += __shfl_xor_sync(0xffffffffu, accA.y, m);
        accA.z += __shfl_xor_sync(0xffffffffu, accA.z, m);
        accA.w += __shfl_xor_sync(0xffffffffu, accA.w, m);
        accB.x += __shfl_xor_sync(0xffffffffu, accB.x, m);
        accB.y += __shfl_xor_sync(0xffffffffu, accB.y, m);
        accB.z += __shfl_xor_sync(0xffffffffu, accB.z, m);
        accB.w += __shfl_xor_sync(0xffffffffu, accB.w, m);
    }
    if ((tid & 31) < 8) {
        red_out[0][warp][c4] = accA;
        red_out[1][warp][c4] = accB;
    }
    __syncthreads();

    if (tid < 8) {
        float4 oA = make_float4(0.f, 0.f, 0.f, 0.f);
        float4 oB = make_float4(0.f, 0.f, 0.f, 0.f);
#pragma unroll
        for (int w = 0; w < 4; ++w) {
            const float4 pA = red_out[0][w][c4];
            const float4 pB = red_out[1][w][c4];
            oA.x += pA.x; oA.y += pA.y; oA.z += pA.z; oA.w += pA.w;
            oB.x += pB.x; oB.y += pB.y; oB.z += pB.z; oB.w += pB.w;
        }
        ((float4*)(out + (size_t)bh * DV))[colA] = oA;
        ((float4*)(out + (size_t)bh * DV))[colB] = oB;
    }
}

extern "C" void kernel_launch(void* const* d_in, const int* in_sizes, int n_in,
                              void* d_out, int out_size)
{
    const float* q     = (const float*)d_in[0];  // (B,H,1,Dk)
    const float* k     = (const float*)d_in[1];  // (B,H,1,Dk)
    const float* v     = (const float*)d_in[2];  // (B,H,1,Dv)
    const float* g     = (const float*)d_in[3];  // (B,H,1)
    const float* beta  = (const float*)d_in[4];  // (B,H,1)
    const float* state = (const float*)d_in[5];  // (B,H,Dk,Dv)

    float* out       = (float*)d_out;            // first B*H*Dv floats
    float* state_out = out + (size_t)BH * DV;    // then B*H*Dk*Dv floats

    delta_cell_kernel<<<BH * 2, 128>>>(q, k, v, g, beta, state,
                                       out, state_out);
}

// round 15
// speedup vs baseline: 1.0346x; 1.0346x over previous
#include <cuda_runtime.h>
#include <cstdint>

// Gated delta-rule recurrent attention, single step. B=128, H=16, Dk=Dv=128.
//
// Round-14 = r7 shape (best) + algebraic epilogue restructuring:
//   out[v] = sum_i q_i*sn_i = decay*(sum_i q_i*s_i) + (sum_i q_i*k_i)*delta[v]
// so the q-dot moves into pass 1 (second fma chain on the loaded patch,
// plus one scalar q.k partial), sharing the SAME shuffle+barrier reduction
// as the k-dot. Pass 2 becomes a pure fma+STG burst; the third barrier and
// second reduce epoch are eliminated (3 barriers -> 2), and out is written
// immediately after delta.
//
// Shape (proven): 8192 CTAs x 128 threads, 32-col slices, s[8] float4 regs,
// __ldcs/__stcs, 8 CTAs/SM.

#define BH   2048
#define DK   128
#define DV   128

__global__ __launch_bounds__(128, 8)
void delta_cell_kernel(const float* __restrict__ q,
                       const float* __restrict__ k,
                       const float* __restrict__ v,
                       const float* __restrict__ g,
                       const float* __restrict__ beta,
                       const float* __restrict__ state_in,
                       float* __restrict__ out,
                       float* __restrict__ state_out)
{
    const int bid  = blockIdx.x;         // 0..8191
    const int bh   = bid >> 2;           // (b*H + h)
    const int cb   = bid & 3;            // column block: cols [cb*32, cb*32+32)
    const int tid  = threadIdx.x;
    const int c4   = tid & 7;            // float4 col within slice (0..7)
    const int rg   = tid >> 3;           // row group (0..15), rows 8rg..8rg+7
    const int warp = tid >> 5;           // 0..3
    const int lane = tid & 31;

    __shared__ float  ks[DK];
    __shared__ float  qs[DK];
    __shared__ float4 red_kv[4][8];      // k-dot partial per warp per c4
    __shared__ float4 red_qd[4][8];      // q-dot partial per warp per c4
    __shared__ float  red_qk[4];         // scalar q.k partial per warp

    const float4* __restrict__ st4 =
        (const float4*)(state_in  + (size_t)bh * DK * DV);
    float4* __restrict__ sto4 =
        (float4*)(state_out + (size_t)bh * DK * DV);
    const int colbase = cb * 8 + c4;     // float4 column in the 32-wide row

    // ---- Front-batched state loads (no dependency on k/q) ----
    float4 s[8];
#pragma unroll
    for (int j = 0; j < 8; ++j)
        s[j] = __ldcs(&st4[(rg * 8 + j) * 32 + colbase]);

    // Small tensors + k/q staging ride under the state-load latency.
    const float4 vt   = ((const float4*)(v + (size_t)bh * DV))[cb * 8 + c4];
    const float decay = expf(g[bh]);
    const float bet   = beta[bh];
    ks[tid] = k[bh * DK + tid];
    qs[tid] = q[bh * DK + tid];
    __syncthreads();

    // ---- Pass 1: k-dot, q-dot, and scalar q.k partials over the patch ----
    float4 kv = make_float4(0.f, 0.f, 0.f, 0.f);
    float4 qd = make_float4(0.f, 0.f, 0.f, 0.f);
    float  qk = 0.f;
#pragma unroll
    for (int j = 0; j < 8; ++j) {
        const int row = rg * 8 + j;
        const float kk = ks[row];
        const float qq = qs[row];
        kv.x = fmaf(s[j].x, kk, kv.x);
        kv.y = fmaf(s[j].y, kk, kv.y);
        kv.z = fmaf(s[j].z, kk, kv.z);
        kv.w = fmaf(s[j].w, kk, kv.w);
        qd.x = fmaf(s[j].x, qq, qd.x);
        qd.y = fmaf(s[j].y, qq, qd.y);
        qd.z = fmaf(s[j].z, qq, qd.z);
        qd.w = fmaf(s[j].w, qq, qd.w);
        qk   = fmaf(kk, qq, qk);        // c4-redundant; summed over rg below
    }
    // Collapse the 4 row-groups within the warp (lane xor 8/16 keeps c4).
#pragma unroll
    for (int m = 8; m <= 16; m <<= 1) {
        kv.x += __shfl_xor_sync(0xffffffffu, kv.x, m);
        kv.y += __shfl_xor_sync(0xffffffffu, kv.y, m);
        kv.z += __shfl_xor_sync(0xffffffffu, kv.z, m);
        kv.w += __shfl_xor_sync(0xffffffffu, kv.w, m);
        qd.x += __shfl_xor_sync(0xffffffffu, qd.x, m);
        qd.y += __shfl_xor_sync(0xffffffffu, qd.y, m);
        qd.z += __shfl_xor_sync(0xffffffffu, qd.z, m);
        qd.w += __shfl_xor_sync(0xffffffffu, qd.w, m);
        qk   += __shfl_xor_sync(0xffffffffu, qk, m);
    }
    if (lane < 8) {
        red_kv[warp][c4] = kv;
        red_qd[warp][c4] = qd;
        if (lane == 0) red_qk[warp] = qk;
    }
    __syncthreads();   // the ONLY reduction barrier

    // ---- Totals + delta (redundantly in every thread) ----
    float4 kvt = make_float4(0.f, 0.f, 0.f, 0.f);
    float4 qdt = make_float4(0.f, 0.f, 0.f, 0.f);
#pragma unroll
    for (int w = 0; w < 4; ++w) {
        const float4 a = red_kv[w][c4];
        const float4 b = red_qd[w][c4];
        kvt.x += a.x; kvt.y += a.y; kvt.z += a.z; kvt.w += a.w;
        qdt.x += b.x; qdt.y += b.y; qdt.z += b.z; qdt.w += b.w;
    }
    const float qkt = red_qk[0] + red_qk[1] + red_qk[2] + red_qk[3];

    // kv_mem = decay*(state.k); delta = (v - kv_mem)*beta
    float4 delta;
    delta.x = (vt.x - decay * kvt.x) * bet;
    delta.y = (vt.y - decay * kvt.y) * bet;
    delta.z = (vt.z - decay * kvt.z) * bet;
    delta.w = (vt.w - decay * kvt.w) * bet;

    // out = decay*(q.state) + (q.k)*delta  -- written before the store burst
    if (tid < 8) {
        float4 o;
        o.x = fmaf(decay, qdt.x, qkt * delta.x);
        o.y = fmaf(decay, qdt.y, qkt * delta.y);
        o.z = fmaf(decay, qdt.z, qkt * delta.z);
        o.w = fmaf(decay, qdt.w, qkt * delta.w);
        ((float4*)(out + (size_t)bh * DV))[cb * 8 + c4] = o;
    }

    // ---- Pass 2: pure store burst, no trailing reduction or barrier ----
#pragma unroll
    for (int j = 0; j < 8; ++j) {
        const int row = rg * 8 + j;
        const float kk = ks[row];
        float4 sn;
        sn.x = fmaf(decay, s[j].x, kk * delta.x);
        sn.y = fmaf(decay, s[j].y, kk * delta.y);
        sn.z = fmaf(decay, s[j].z, kk * delta.z);
        sn.w = fmaf(decay, s[j].w, kk * delta.w);
        __stcs(&sto4[row * 32 + colbase], sn);
    }
}

extern "C" void kernel_launch(void* const* d_in, const int* in_sizes, int n_in,
                              void* d_out, int out_size)
{
    const float* q     = (const float*)d_in[0];  // (B,H,1,Dk)
    const float* k     = (const float*)d_in[1];  // (B,H,1,Dk)
    const float* v     = (const float*)d_in[2];  // (B,H,1,Dv)
    const float* g     = (const float*)d_in[3];  // (B,H,1)
    const float* beta  = (const float*)d_in[4];  // (B,H,1)
    const float* state = (const float*)d_in[5];  // (B,H,Dk,Dv)

    float* out       = (float*)d_out;            // first B*H*Dv floats
    float* state_out = out + (size_t)BH * DV;    // then B*H*Dk*Dv floats

    delta_cell_kernel<<<BH * 4, 128>>>(q, k, v, g, beta, state,
                                       out, state_out);
}